// round 9
// baseline (speedup 1.0000x reference)
#include <cuda_runtime.h>
#include <math.h>

// ---------------- fixed CT geometry ----------------
#define IMG   512
#define NDET  768
#define NV    360
#define GLEN  (2*NDET-1)

#define PIXd  0.7433
#define DSOd  595.0
#define DSDd  1085.6              // 595.0 + 490.6
#define DETd  1.2858
#define DGd   (DETd / DSDd)       // equiangular pitch (rad/bin)
#define INVDGd (DSDd / DETd)
#define SCALEd (DGd * 2.0 * M_PI / 360.0)   // fold q*=DGAMMA and *=2pi/NV

// padded q row: [16 zero | 768 data | 16 zero]; i0 in [-13,779] stays in-row
#define QPAD    16
#define QSTRIDE 800

// ---------------- device scratch (no allocations allowed) ----------------
__device__ float  g_tab[GLEN];              // ramp taps (prescaled)
__device__ float2 cs_tab[NV];               // (cos beta, sin beta)
__device__ float2 p1_buf[NV * NDET];        // cosine-weighted projections
__device__ float2 q_raw[NV * NDET];         // conv output (q0, q1) per det
__device__ float4 q_pack[NV * QSTRIDE];     // (q0, dq0, q1, dq1), zero-padded
__device__ float  part_img[3][2 * IMG * IMG]; // rot-90/180/270 contributions

// ---------------- prep: ramp table + angles + cosine weighting -------------
__global__ void __launch_bounds__(NDET) prep_kernel(const float* __restrict__ proj) {
    const int v = blockIdx.x;
    const int t = threadIdx.x;

    if (v == 0) {                            // ramp taps, once (fp32: 2e-7 rel)
        for (int i = t; i < GLEN; i += NDET) {
            int n = i - (NDET - 1);
            float g;
            if (n == 0) {
                g = (float)(SCALEd / (8.0 * DGd * DGd));
            } else if (n & 1) {
                float s = sinf((float)n * (float)DGd) * (float)M_PI;
                g = (float)(-0.5 * SCALEd) / (s * s);
            } else {
                g = 0.0f;
            }
            g_tab[i] = g;
        }
    }
    if (t == 0) {
        double sb, cb;
        sincospi((double)v / 180.0, &sb, &cb);
        cs_tab[v] = make_float2((float)cb, (float)sb);
    }
    float gam = ((float)t - 383.5f) * (float)DGd;
    float cw  = 595.0f * cosf(gam);          // DSO * cos(gamma)
    p1_buf[v * NDET + t] = make_float2(proj[(0 * NV + v) * NDET + t] * cw,
                                       proj[(1 * NV + v) * NDET + t] * cw);
}

// ---------------- conv: 2 blocks per view, 384 outputs each ----------------
__global__ void __launch_bounds__(384) conv_kernel() {
    __shared__ float2 p2[NDET];
    __shared__ float  gs[GLEN];

    const int v    = blockIdx.x >> 1;
    const int half = blockIdx.x & 1;
    const int tid  = threadIdx.x;
    const int t    = half * 384 + tid;       // this thread's output bin

    for (int i = tid; i < GLEN; i += 384) gs[i] = g_tab[i];      // coalesced
    p2[tid]       = p1_buf[v * NDET + tid];
    p2[tid + 384] = p1_buf[v * NDET + tid + 384];
    __syncthreads();

    float2 pc = p2[t];
    const float g0 = gs[NDET - 1];
    float a0 = pc.x * g0;
    float a1 = pc.y * g0;
    const int k0 = (t + 1) & 1;              // k parity making t-k odd
#pragma unroll 8
    for (int k = k0; k < NDET; k += 2) {
        float gv = gs[t - k + (NDET - 1)];
        float2 p = p2[k];
        a0 = fmaf(p.x, gv, a0);
        a1 = fmaf(p.y, gv, a1);
    }
    q_raw[v * NDET + t] = make_float2(a0, a1);
}

// ---------------- pack: neighbor pre-diff + interleave + pads --------------
__global__ void __launch_bounds__(NDET) pack_kernel() {
    const int v = blockIdx.x;
    const int t = threadIdx.x;

    if (t < QPAD) {
        q_pack[v * QSTRIDE + t]               = make_float4(0.f, 0.f, 0.f, 0.f);
        q_pack[v * QSTRIDE + QPAD + NDET + t] = make_float4(0.f, 0.f, 0.f, 0.f);
    }
    float2 qa = q_raw[v * NDET + t];
    float2 qb = q_raw[v * NDET + min(t + 1, NDET - 1)];
    q_pack[v * QSTRIDE + QPAD + t] =
        make_float4(qa.x, qb.x - qa.x, qa.y, qb.y - qa.y);
}

// ---------------- backprojection with 4-fold rotation symmetry -------------
// geom((x,y), beta) == geom((-y,x), beta+pi/2) == ... (exact).
// One geometry+asin serves 4 pixel-view updates; loop is views 0..89.
// Warp tiling 8x4: minimizes per-warp detector-index spread so each LDG.128
// touches ~2 cache lines instead of 4-5 (bp is L1TEX-wavefront bound).
__global__ void __launch_bounds__(256, 6) bp_kernel(float* __restrict__ out) {
    __shared__ float2 cs_s[NV / 4];
    const int tid = threadIdx.x;
    if (tid < NV / 4) cs_s[tid] = cs_tab[tid];
    __syncthreads();

    const int w = tid >> 5, l = tid & 31;    // warp covers 8x4 pixels
    const int j = (blockIdx.x << 4) + (l & 7) + ((w & 1) << 3);
    const int i = (blockIdx.y << 4) + (l >> 3) + ((w >> 1) << 2);

    const float x = ((float)j - 255.5f) * (float)PIXd;
    const float y = ((float)i - 255.5f) * (float)PIXd;
    const float DSOf = 595.0f;

    // asin Taylor coefficients * (1/DGAMMA)
    const float A0 = (float)(INVDGd);
    const float A1 = (float)(INVDGd / 6.0);
    const float A2 = (float)(INVDGd * 0.075);
    const float A3 = (float)(INVDGd * 0.044642857);
    const float A4 = (float)(INVDGd * 0.030381944);
    const float A5 = (float)(INVDGd * 0.022372159);
    const float A6 = (float)(INVDGd * 0.017352764);
    const float A7 = (float)(INVDGd * 0.013964844);

    float aS0 = 0.f, aS1 = 0.f;              // self pixel,     views 0..89
    float a90_0 = 0.f, a90_1 = 0.f;          // rot +90 pixel,  views 90..179
    float a180_0 = 0.f, a180_1 = 0.f;        // rot 180 pixel,  views 180..269
    float a270_0 = 0.f, a270_1 = 0.f;        // rot 270 pixel,  views 270..359

    const float4* __restrict__ qp = q_pack + QPAD;

#pragma unroll 3
    for (int v = 0; v < NV / 4; ++v) {
        float2 cs = cs_s[v];
        float u  = fmaf(cs.x, x,  cs.y * y);
        float cr = fmaf(cs.y, x, -cs.x * y);
        float dt = DSOf - u;
        float L2 = fmaf(dt, dt, cr * cr);
        float rsq;
        asm("rsqrt.approx.f32 %0, %1;" : "=f"(rsq) : "f"(L2));
        float s  = cr * rsq;                 // sin(theta), dt > 0 always
        float s2 = s * s;
        float p  = fmaf(A7, s2, A6);
        p = fmaf(p, s2, A5);
        p = fmaf(p, s2, A4);
        p = fmaf(p, s2, A3);
        p = fmaf(p, s2, A2);
        p = fmaf(p, s2, A1);
        p = fmaf(p, s2, A0);
        float tv = s * p;                    // g - 383.5 (detector offset)
        float g  = tv + 383.5f;

        float T  = (g - 0.5f) + 12582912.0f; // round(g-0.5) == floor(g)
        int   i0 = __float_as_int(T) - 0x4B400000;
        float fg = T - 12582912.0f;
        float w_ = g - fg;
        float m  = rsq * rsq;                // 1/L2
        float wl = (fabsf(tv) <= 383.5f) ? m : 0.0f;   // g in [0,767]

        const float4* qv = qp + v * QSTRIDE + i0;
        float4 qa = qv[0];                          // view v
        float4 qb = qv[ 90 * QSTRIDE];              // view v+90
        float4 qc = qv[180 * QSTRIDE];              // view v+180
        float4 qd = qv[270 * QSTRIDE];              // view v+270
        aS0    = fmaf(fmaf(w_, qa.y, qa.x), wl, aS0);
        aS1    = fmaf(fmaf(w_, qa.w, qa.z), wl, aS1);
        a90_0  = fmaf(fmaf(w_, qb.y, qb.x), wl, a90_0);
        a90_1  = fmaf(fmaf(w_, qb.w, qb.z), wl, a90_1);
        a180_0 = fmaf(fmaf(w_, qc.y, qc.x), wl, a180_0);
        a180_1 = fmaf(fmaf(w_, qc.w, qc.z), wl, a180_1);
        a270_0 = fmaf(fmaf(w_, qd.y, qd.x), wl, a270_0);
        a270_1 = fmaf(fmaf(w_, qd.w, qd.z), wl, a270_1);
    }

    out[i * IMG + j]             = aS0;
    out[IMG * IMG + i * IMG + j] = aS1;
    // rot +90: pixel (i', j') = (j, 511-i)
    part_img[0][j * IMG + (IMG - 1 - i)]             = a90_0;
    part_img[0][IMG * IMG + j * IMG + (IMG - 1 - i)] = a90_1;
    // rot 180: (511-i, 511-j)
    part_img[1][(IMG - 1 - i) * IMG + (IMG - 1 - j)]             = a180_0;
    part_img[1][IMG * IMG + (IMG - 1 - i) * IMG + (IMG - 1 - j)] = a180_1;
    // rot 270: (511-j, i)
    part_img[2][(IMG - 1 - j) * IMG + i]             = a270_0;
    part_img[2][IMG * IMG + (IMG - 1 - j) * IMG + i] = a270_1;
}

// ---------------- combine: out += s90 + s180 + s270 ------------------------
__global__ void __launch_bounds__(512) combine_kernel(float* __restrict__ out) {
    int t = blockIdx.x * 512 + threadIdx.x;          // float4 index
    float4* o = (float4*)out;
    const float4* p0 = (const float4*)part_img[0];
    const float4* p1 = (const float4*)part_img[1];
    const float4* p2 = (const float4*)part_img[2];
    float4 a = o[t], b = p0[t], c = p1[t], d = p2[t];
    o[t] = make_float4(a.x + b.x + c.x + d.x,
                       a.y + b.y + c.y + d.y,
                       a.z + b.z + c.z + d.z,
                       a.w + b.w + c.w + d.w);
}

// ---------------- entry point ----------------
extern "C" void kernel_launch(void* const* d_in, const int* in_sizes, int n_in,
                              void* d_out, int out_size) {
    (void)in_sizes; (void)n_in; (void)out_size;
    const float* proj = (const float*)d_in[0];   // [2, 360, 768] f32
    float* out = (float*)d_out;                  // [2, 512, 512] f32

    prep_kernel<<<NV, NDET>>>(proj);
    conv_kernel<<<2 * NV, 384>>>();
    pack_kernel<<<NV, NDET>>>();
    bp_kernel<<<dim3(IMG / 16, IMG / 16), 256>>>(out);
    combine_kernel<<<(2 * IMG * IMG / 4) / 512, 512>>>(out);
}

// round 11
// speedup vs baseline: 1.2230x; 1.2230x over previous
#include <cuda_runtime.h>
#include <math.h>

// ---------------- fixed CT geometry ----------------
#define IMG   512
#define NDET  768
#define NV    360
#define GLEN  (2*NDET-1)

#define PIXd  0.7433
#define DSOd  595.0
#define DSDd  1085.6              // 595.0 + 490.6
#define DETd  1.2858
#define DGd   (DETd / DSDd)       // equiangular pitch (rad/bin)
#define INVDGd (DSDd / DETd)
#define SCALEd (DGd * 2.0 * M_PI / 360.0)   // fold q*=DGAMMA and *=2pi/NV

// padded q row: [16 zero | 768 data | 16 zero]; i0 in [-13,779] stays in-row
#define QPAD    16
#define QSTRIDE 800

// ---------------- device scratch (no allocations allowed) ----------------
__device__ float2 cs_tab[NV];               // (cos beta, sin beta)
__device__ float2 q_part[2][NV * NDET];     // split-K partial conv results
__device__ float4 q_pack[NV * QSTRIDE];     // (q0, dq0, q1, dq1), zero-padded
__device__ float  part_img[3][2 * IMG * IMG]; // rot-90/180/270 contributions

// ---------------- conv split-K: block = (view, k-half) ---------------------
// Block h handles taps k in [384h, 384h+384) for all 768 outputs (2/thread).
// gs[0] holds global ramp index idx0 (384 for h=0, 0 for h=1); for output o
// and local tap kk the local index is o - kk + 383 in BOTH halves:
//   h=0: global = o-kk+767, local = global-384 = o-kk+383
//   h=1: global = o-(384+kk)+767 = o-kk+383, local = global-0
__global__ void __launch_bounds__(384) conv_kernel(const float* __restrict__ proj) {
    __shared__ float2 p2[384];               // this half's cosine-weighted bins
    __shared__ float  gs[1151];              // this half's ramp taps

    const int v   = blockIdx.x >> 1;
    const int h   = blockIdx.x & 1;
    const int tid = threadIdx.x;
    const int kbase = h * 384;
    const int idx0  = h ? 0 : 384;           // global g-index of gs[0]

    if (h == 0 && tid == 0) {                // per-view angle (double-accurate)
        double sb, cb;
        sincospi((double)v / 180.0, &sb, &cb);
        cs_tab[v] = make_float2((float)cb, (float)sb);
    }
    // ramp taps for this half
    for (int i = tid; i < 1151; i += 384) {
        int n = (i + idx0) - (NDET - 1);
        float g;
        if (n == 0) {
            g = (float)(SCALEd / (8.0 * DGd * DGd));
        } else if (n & 1) {
            float s = sinf((float)n * (float)DGd) * (float)M_PI;
            g = (float)(-0.5 * SCALEd) / (s * s);
        } else {
            g = 0.0f;
        }
        gs[i] = g;
    }
    {   // cosine-weighted projections for this half's bins
        int bin = kbase + tid;
        float gam = ((float)bin - 383.5f) * (float)DGd;
        float cw  = 595.0f * cosf(gam);
        p2[tid] = make_float2(proj[(0 * NV + v) * NDET + bin] * cw,
                              proj[(1 * NV + v) * NDET + bin] * cw);
    }
    __syncthreads();

    const int t  = tid;                      // output bins t and t+384
    const int t2 = tid + 384;
    const float g0 = (float)(SCALEd / (8.0 * DGd * DGd));

    // center tap (output == k) belongs to the half containing that output
    float a0 = 0.f, a1 = 0.f, b0 = 0.f, b1 = 0.f;
    if (h == 0) { float2 pc = p2[t];         a0 = pc.x * g0; a1 = pc.y * g0; }
    else        { float2 pc = p2[t2 - 384];  b0 = pc.x * g0; b1 = pc.y * g0; }

    const int k0 = (t + 1) & 1;              // parity making (output - k) odd
#pragma unroll 8
    for (int kk = k0; kk < 384; kk += 2) {
        float2 p  = p2[kk];                  // broadcast LDS.64
        float gva = gs[t  - kk + 383];
        float gvb = gs[t2 - kk + 383];       // FIXED: same formula, range <=1150
        a0 = fmaf(p.x, gva, a0);
        a1 = fmaf(p.y, gva, a1);
        b0 = fmaf(p.x, gvb, b0);
        b1 = fmaf(p.y, gvb, b1);
    }
    q_part[h][v * NDET + t]  = make_float2(a0, a1);
    q_part[h][v * NDET + t2] = make_float2(b0, b1);
}

// ---------------- pack: sum halves + pre-diff + interleave + pads ----------
__global__ void __launch_bounds__(NDET) pack_kernel() {
    __shared__ float2 qs[NDET];
    const int v = blockIdx.x;
    const int t = threadIdx.x;

    float2 qa0 = q_part[0][v * NDET + t];
    float2 qa1 = q_part[1][v * NDET + t];
    qs[t] = make_float2(qa0.x + qa1.x, qa0.y + qa1.y);   // fixed order: determ.
    if (t < QPAD) {
        q_pack[v * QSTRIDE + t]               = make_float4(0.f, 0.f, 0.f, 0.f);
        q_pack[v * QSTRIDE + QPAD + NDET + t] = make_float4(0.f, 0.f, 0.f, 0.f);
    }
    __syncthreads();

    float2 qa = qs[t];
    float2 qb = qs[min(t + 1, NDET - 1)];
    q_pack[v * QSTRIDE + QPAD + t] =
        make_float4(qa.x, qb.x - qa.x, qa.y, qb.y - qa.y);
}

// ---------------- backprojection with 4-fold rotation symmetry -------------
// Round-7 proven form (16-wide row-major lanes), 128-thread blocks for
// better wave balance (2048 CTAs -> 13.8/SM).
__global__ void __launch_bounds__(128, 12) bp_kernel(float* __restrict__ out) {
    __shared__ float2 cs_s[NV / 4];
    const int tid = threadIdx.y * 16 + threadIdx.x;
    if (tid < NV / 4) cs_s[tid] = cs_tab[tid];
    __syncthreads();

    const int j = (blockIdx.x << 4) + threadIdx.x;
    const int i = (blockIdx.y << 3) + threadIdx.y;

    const float x = ((float)j - 255.5f) * (float)PIXd;
    const float y = ((float)i - 255.5f) * (float)PIXd;
    const float DSOf = 595.0f;

    // asin Taylor coefficients * (1/DGAMMA)
    const float A0 = (float)(INVDGd);
    const float A1 = (float)(INVDGd / 6.0);
    const float A2 = (float)(INVDGd * 0.075);
    const float A3 = (float)(INVDGd * 0.044642857);
    const float A4 = (float)(INVDGd * 0.030381944);
    const float A5 = (float)(INVDGd * 0.022372159);
    const float A6 = (float)(INVDGd * 0.017352764);
    const float A7 = (float)(INVDGd * 0.013964844);

    float aS0 = 0.f, aS1 = 0.f;              // self pixel,     views 0..89
    float a90_0 = 0.f, a90_1 = 0.f;          // rot +90 pixel,  views 90..179
    float a180_0 = 0.f, a180_1 = 0.f;        // rot 180 pixel,  views 180..269
    float a270_0 = 0.f, a270_1 = 0.f;        // rot 270 pixel,  views 270..359

    const float4* __restrict__ qp = q_pack + QPAD;

#pragma unroll 3
    for (int v = 0; v < NV / 4; ++v) {
        float2 cs = cs_s[v];
        float u  = fmaf(cs.x, x,  cs.y * y);
        float cr = fmaf(cs.y, x, -cs.x * y);
        float dt = DSOf - u;
        float L2 = fmaf(dt, dt, cr * cr);
        float rsq;
        asm("rsqrt.approx.f32 %0, %1;" : "=f"(rsq) : "f"(L2));
        float s  = cr * rsq;                 // sin(theta), dt > 0 always
        float s2 = s * s;
        float p  = fmaf(A7, s2, A6);
        p = fmaf(p, s2, A5);
        p = fmaf(p, s2, A4);
        p = fmaf(p, s2, A3);
        p = fmaf(p, s2, A2);
        p = fmaf(p, s2, A1);
        p = fmaf(p, s2, A0);
        float tv = s * p;                    // g - 383.5 (detector offset)
        float g  = tv + 383.5f;

        float T  = (g - 0.5f) + 12582912.0f; // round(g-0.5) == floor(g)
        int   i0 = __float_as_int(T) - 0x4B400000;
        float fg = T - 12582912.0f;
        float w_ = g - fg;
        float m  = rsq * rsq;                // 1/L2
        float wl = (fabsf(tv) <= 383.5f) ? m : 0.0f;   // g in [0,767]

        const float4* qv = qp + v * QSTRIDE + i0;
        float4 qa = qv[0];                          // view v
        float4 qb = qv[ 90 * QSTRIDE];              // view v+90
        float4 qc = qv[180 * QSTRIDE];              // view v+180
        float4 qd = qv[270 * QSTRIDE];              // view v+270
        aS0    = fmaf(fmaf(w_, qa.y, qa.x), wl, aS0);
        aS1    = fmaf(fmaf(w_, qa.w, qa.z), wl, aS1);
        a90_0  = fmaf(fmaf(w_, qb.y, qb.x), wl, a90_0);
        a90_1  = fmaf(fmaf(w_, qb.w, qb.z), wl, a90_1);
        a180_0 = fmaf(fmaf(w_, qc.y, qc.x), wl, a180_0);
        a180_1 = fmaf(fmaf(w_, qc.w, qc.z), wl, a180_1);
        a270_0 = fmaf(fmaf(w_, qd.y, qd.x), wl, a270_0);
        a270_1 = fmaf(fmaf(w_, qd.w, qd.z), wl, a270_1);
    }

    out[i * IMG + j]             = aS0;
    out[IMG * IMG + i * IMG + j] = aS1;
    // rot +90: pixel (i', j') = (j, 511-i)
    part_img[0][j * IMG + (IMG - 1 - i)]             = a90_0;
    part_img[0][IMG * IMG + j * IMG + (IMG - 1 - i)] = a90_1;
    // rot 180: (511-i, 511-j)
    part_img[1][(IMG - 1 - i) * IMG + (IMG - 1 - j)]             = a180_0;
    part_img[1][IMG * IMG + (IMG - 1 - i) * IMG + (IMG - 1 - j)] = a180_1;
    // rot 270: (511-j, i)
    part_img[2][(IMG - 1 - j) * IMG + i]             = a270_0;
    part_img[2][IMG * IMG + (IMG - 1 - j) * IMG + i] = a270_1;
}

// ---------------- combine: out += s90 + s180 + s270 ------------------------
__global__ void __launch_bounds__(512) combine_kernel(float* __restrict__ out) {
    int t = blockIdx.x * 512 + threadIdx.x;          // float4 index
    float4* o = (float4*)out;
    const float4* p0 = (const float4*)part_img[0];
    const float4* p1 = (const float4*)part_img[1];
    const float4* p2 = (const float4*)part_img[2];
    float4 a = o[t], b = p0[t], c = p1[t], d = p2[t];
    o[t] = make_float4(a.x + b.x + c.x + d.x,
                       a.y + b.y + c.y + d.y,
                       a.z + b.z + c.z + d.z,
                       a.w + b.w + c.w + d.w);
}

// ---------------- entry point ----------------
extern "C" void kernel_launch(void* const* d_in, const int* in_sizes, int n_in,
                              void* d_out, int out_size) {
    (void)in_sizes; (void)n_in; (void)out_size;
    const float* proj = (const float*)d_in[0];   // [2, 360, 768] f32
    float* out = (float*)d_out;                  // [2, 512, 512] f32

    conv_kernel<<<2 * NV, 384>>>(proj);
    pack_kernel<<<NV, NDET>>>();
    bp_kernel<<<dim3(IMG / 16, IMG / 8), dim3(16, 8)>>>(out);
    combine_kernel<<<(2 * IMG * IMG / 4) / 512, 512>>>(out);
}